// round 1
// baseline (speedup 1.0000x reference)
#include <cuda_runtime.h>
#include <cstdint>

#define D_MODEL 1024
#define D_STATE 16
#define BATCH   4
#define SEQLEN  4096
#define NROWS   (BATCH*SEQLEN)      // 16384
#define CHUNK   64
#define NCHUNK  (SEQLEN/CHUNK)      // 64

// ---------------- device scratch (no allocations allowed) ----------------
__device__ float g_bx   [NROWS * D_STATE];   // 1 MB
__device__ float g_decay[NROWS * D_STATE];   // 1 MB
__device__ float g_h0   [BATCH * NCHUNK * D_STATE]; // chunk-entry states

// ---------------- f32x2 helpers ----------------
static __device__ __forceinline__ unsigned long long pack2(float lo, float hi) {
    unsigned long long r;
    asm("mov.b64 %0, {%1, %2};" : "=l"(r) : "f"(lo), "f"(hi));
    return r;
}
static __device__ __forceinline__ void unpack2(unsigned long long v, float& lo, float& hi) {
    asm("mov.b64 {%0, %1}, %2;" : "=f"(lo), "=f"(hi) : "l"(v));
}
static __device__ __forceinline__ unsigned long long fma2(unsigned long long a, unsigned long long b, unsigned long long c) {
    unsigned long long d;
    asm("fma.rn.f32x2 %0, %1, %2, %3;" : "=l"(d) : "l"(a), "l"(b), "l"(c));
    return d;
}
static __device__ __forceinline__ unsigned long long mul2(unsigned long long a, unsigned long long b) {
    unsigned long long d;
    asm("mul.rn.f32x2 %0, %1, %2;" : "=l"(d) : "l"(a), "l"(b));
    return d;
}

// =======================================================================
// K1: Bx = x @ B_in ; decay = exp(softplus(Bx) * (-exp(A)))
// grid 128 blocks x 128 threads; warp handles 32 consecutive rows (1/lane).
// B_in in smem (broadcast), x staged via xor-swizzled smem transpose.
// =======================================================================
__global__ void __launch_bounds__(128) k_bxdecay(const float* __restrict__ x,
                                                 const float* __restrict__ A,
                                                 const float* __restrict__ Bin)
{
    extern __shared__ float smem[];
    float* sB = smem;                 // 16384 floats (64 KB)
    float* xt = smem + 16384;         // 4 warps * 4096 floats (64 KB)
    __shared__ float sA[16];

    const int tid  = threadIdx.x;
    const int w    = tid >> 5;
    const int lane = tid & 31;

    // load B_in into smem (coalesced float4)
    {
        const float4* B4 = (const float4*)Bin;
        float4* sB4 = (float4*)sB;
        #pragma unroll 8
        for (int i = tid; i < 4096; i += 128) sB4[i] = B4[i];
    }
    if (tid < 16) sA[tid] = -expf(A[tid]);
    __syncthreads();

    float* xtw = xt + w * 4096;
    const int rowBase = blockIdx.x * 128 + w * 32;

    unsigned long long acc[8];
    #pragma unroll
    for (int j = 0; j < 8; j++) acc[j] = 0ull;

    const ulonglong2* sBu = (const ulonglong2*)sB;
    const float4* x4 = (const float4*)x;

    for (int et = 0; et < D_MODEL; et += 128) {
        // ---- stage: warp loads one row at a time (coalesced 512B),
        //      stores transposed with xor swizzle (conflict-free) ----
        const int e0 = 4 * lane;
        #pragma unroll 4
        for (int r = 0; r < 32; r++) {
            float4 xv = __ldg(x4 + (size_t)(rowBase + r) * 256 + (et >> 2) + lane);
            xtw[(e0+0)*32 + (r ^ ((e0+0) & 31))] = xv.x;
            xtw[(e0+1)*32 + (r ^ ((e0+1) & 31))] = xv.y;
            xtw[(e0+2)*32 + (r ^ ((e0+2) & 31))] = xv.z;
            xtw[(e0+3)*32 + (r ^ ((e0+3) & 31))] = xv.w;
        }
        __syncwarp();

        // ---- compute: per e, broadcast B row + per-lane x, 8 f32x2 FMAs ----
        #pragma unroll 8
        for (int el = 0; el < 128; el++) {
            float xv = xtw[el*32 + (lane ^ (el & 31))];
            unsigned long long xx = pack2(xv, xv);
            int e = et + el;
            ulonglong2 q0 = sBu[e*4 + 0];
            ulonglong2 q1 = sBu[e*4 + 1];
            ulonglong2 q2 = sBu[e*4 + 2];
            ulonglong2 q3 = sBu[e*4 + 3];
            acc[0] = fma2(q0.x, xx, acc[0]);
            acc[1] = fma2(q0.y, xx, acc[1]);
            acc[2] = fma2(q1.x, xx, acc[2]);
            acc[3] = fma2(q1.y, xx, acc[3]);
            acc[4] = fma2(q2.x, xx, acc[4]);
            acc[5] = fma2(q2.y, xx, acc[5]);
            acc[6] = fma2(q3.x, xx, acc[6]);
            acc[7] = fma2(q3.y, xx, acc[7]);
        }
        __syncwarp();
    }

    // ---- epilogue: softplus / decay, write coalesced ----
    const int row = rowBase + lane;
    float bx[16], dc[16];
    #pragma unroll
    for (int j = 0; j < 8; j++) unpack2(acc[j], bx[2*j], bx[2*j+1]);
    #pragma unroll
    for (int s = 0; s < 16; s++) {
        float u  = bx[s];
        float sp = fmaxf(u, 0.0f) + log1pf(expf(-fabsf(u)));  // stable softplus
        dc[s] = expf(sp * sA[s]);
    }
    float4* gb4 = (float4*)g_bx;
    float4* gd4 = (float4*)g_decay;
    #pragma unroll
    for (int q = 0; q < 4; q++) {
        gb4[row*4 + q] = make_float4(bx[4*q], bx[4*q+1], bx[4*q+2], bx[4*q+3]);
        gd4[row*4 + q] = make_float4(dc[4*q], dc[4*q+1], dc[4*q+2], dc[4*q+3]);
    }
}

// =======================================================================
// K2: chunk aggregates + scan of chunk boundaries -> g_h0
// one block per batch; thread (chunk c, state s)
// =======================================================================
__global__ void __launch_bounds__(1024) k_scan()
{
    __shared__ float sa[NCHUNK * D_STATE];
    __shared__ float sv[NCHUNK * D_STATE];
    const int b   = blockIdx.x;
    const int tid = threadIdx.x;
    const int c   = tid >> 4;
    const int s   = tid & 15;

    int base = (b * SEQLEN + c * CHUNK) * D_STATE + s;
    float a = 1.0f, v = 0.0f;
    #pragma unroll 4
    for (int t = 0; t < CHUNK; t++) {
        float d   = g_decay[base + t * D_STATE];
        float bxv = g_bx   [base + t * D_STATE];
        v = fmaf(v, d, bxv);
        a *= d;
    }
    sa[c * 16 + s] = a;
    sv[c * 16 + s] = v;
    __syncthreads();

    if (tid < 16) {
        float h = 0.0f;
        for (int cc = 0; cc < NCHUNK; cc++) {
            g_h0[(b * NCHUNK + cc) * 16 + tid] = h;           // state entering chunk cc
            h = fmaf(sa[cc * 16 + tid], h, sv[cc * 16 + tid]);
        }
    }
}

// =======================================================================
// K3: per-chunk local scan (lanes 0..15) + y = h @ C + x*D
// grid = BATCH*NCHUNK blocks x 256 threads (thread -> 4 output columns)
// C held in registers as f32x2 pairs; x loaded ONLY where D != 0.
// =======================================================================
__global__ void __launch_bounds__(256) k_out(const float* __restrict__ x,
                                             const float* __restrict__ C,
                                             const float* __restrict__ D,
                                             float* __restrict__ y)
{
    __shared__ __align__(16) float hh[CHUNK][16];
    const int b    = blockIdx.x >> 6;
    const int c    = blockIdx.x & 63;
    const int tid  = threadIdx.x;
    const int row0 = b * SEQLEN + c * CHUNK;

    // C tile into registers (f32x2 pairs): 16 states x 4 columns
    unsigned long long ca[16], cb[16];
    #pragma unroll
    for (int s = 0; s < 16; s++) {
        float4 cv = __ldg((const float4*)C + s * 256 + tid);
        ca[s] = pack2(cv.x, cv.y);
        cb[s] = pack2(cv.z, cv.w);
    }
    float4 dv = __ldg((const float4*)D + tid);
    bool anyD = (dv.x != 0.0f) || (dv.y != 0.0f) || (dv.z != 0.0f) || (dv.w != 0.0f);
    unsigned long long d01 = pack2(dv.x, dv.y);
    unsigned long long d23 = pack2(dv.z, dv.w);

    // ---- local scan by lanes 0..15 of warp 0, software-pipelined ----
    if (tid < 16) {
        float h = g_h0[(b * NCHUNK + c) * 16 + tid];
        int base = row0 * D_STATE + tid;
        float dA[8], vA[8], dB[8], vB[8];
        #pragma unroll
        for (int k = 0; k < 8; k++) {
            dA[k] = g_decay[base + k * 16];
            vA[k] = g_bx   [base + k * 16];
        }
        #pragma unroll
        for (int g = 0; g < 8; g++) {
            if (g < 7) {
                #pragma unroll
                for (int k = 0; k < 8; k++) {
                    dB[k] = g_decay[base + ((g+1)*8 + k) * 16];
                    vB[k] = g_bx   [base + ((g+1)*8 + k) * 16];
                }
            }
            #pragma unroll
            for (int k = 0; k < 8; k++) {
                h = fmaf(h, dA[k], vA[k]);
                hh[g*8 + k][tid] = h;
            }
            #pragma unroll
            for (int k = 0; k < 8; k++) { dA[k] = dB[k]; vA[k] = vB[k]; }
        }
    }
    __syncthreads();

    const float4* x4 = (const float4*)x;
    float4* y4 = (float4*)y;

    #pragma unroll 2
    for (int t = 0; t < CHUNK; t++) {
        unsigned long long y01, y23;
        if (anyD) {
            float4 xv = __ldg(x4 + (size_t)(row0 + t) * 256 + tid);
            y01 = mul2(pack2(xv.x, xv.y), d01);
            y23 = mul2(pack2(xv.z, xv.w), d23);
        } else {
            y01 = 0ull; y23 = 0ull;
        }
        const float4* hf = (const float4*)hh[t];  // broadcast, conflict-free
        float4 h0 = hf[0], h1 = hf[1], h2 = hf[2], h3 = hf[3];

        #define SSTEP(hv, s) { unsigned long long hs = pack2((hv), (hv)); \
                               y01 = fma2(hs, ca[s], y01);                \
                               y23 = fma2(hs, cb[s], y23); }
        SSTEP(h0.x, 0)  SSTEP(h0.y, 1)  SSTEP(h0.z, 2)  SSTEP(h0.w, 3)
        SSTEP(h1.x, 4)  SSTEP(h1.y, 5)  SSTEP(h1.z, 6)  SSTEP(h1.w, 7)
        SSTEP(h2.x, 8)  SSTEP(h2.y, 9)  SSTEP(h2.z,10)  SSTEP(h2.w,11)
        SSTEP(h3.x,12)  SSTEP(h3.y,13)  SSTEP(h3.z,14)  SSTEP(h3.w,15)
        #undef SSTEP

        float4 out;
        unpack2(y01, out.x, out.y);
        unpack2(y23, out.z, out.w);
        y4[(size_t)(row0 + t) * 256 + tid] = out;
    }
}

// =======================================================================
extern "C" void kernel_launch(void* const* d_in, const int* in_sizes, int n_in,
                              void* d_out, int out_size)
{
    const float* x   = (const float*)d_in[0];
    const float* A   = (const float*)d_in[1];
    const float* Bin = (const float*)d_in[2];
    const float* C   = (const float*)d_in[3];
    const float* D   = (const float*)d_in[4];
    float* y = (float*)d_out;

    // 128 KB dynamic smem for K1 (B_in 64KB + per-warp x transpose 64KB)
    cudaFuncSetAttribute(k_bxdecay, cudaFuncAttributeMaxDynamicSharedMemorySize, 131072);

    k_bxdecay<<<NROWS / 128, 128, 131072>>>(x, A, Bin);
    k_scan<<<BATCH, 1024>>>();
    k_out<<<BATCH * NCHUNK, 256>>>(x, C, D, y);
}

// round 5
// speedup vs baseline: 1.8324x; 1.8324x over previous
#include <cuda_runtime.h>
#include <cstdint>

#define D_MODEL 1024
#define D_STATE 16
#define BATCH   4
#define SEQLEN  4096
#define NROWS   (BATCH*SEQLEN)      // 16384
#define CHUNK2  32
#define NCHUNK2 (SEQLEN/CHUNK2)     // 128
#define ESPLIT  8
#define EB      (D_MODEL/ESPLIT)    // 128 e's per block in K1

// ---------------- device scratch (no allocations allowed) ----------------
__device__ float g_bxp  [ESPLIT][NROWS * D_STATE]; // 8 MB partials
__device__ float g_bx   [NROWS * D_STATE];         // 1 MB
__device__ float g_decay[NROWS * D_STATE];         // 1 MB
__device__ float g_h0   [BATCH * NCHUNK2 * D_STATE];

// ---------------- f32x2 helpers ----------------
static __device__ __forceinline__ unsigned long long pack2(float lo, float hi) {
    unsigned long long r;
    asm("mov.b64 %0, {%1, %2};" : "=l"(r) : "f"(lo), "f"(hi));
    return r;
}
static __device__ __forceinline__ void unpack2(unsigned long long v, float& lo, float& hi) {
    asm("mov.b64 {%0, %1}, %2;" : "=f"(lo), "=f"(hi) : "l"(v));
}
static __device__ __forceinline__ unsigned long long fma2(unsigned long long a, unsigned long long b, unsigned long long c) {
    unsigned long long d;
    asm("fma.rn.f32x2 %0, %1, %2, %3;" : "=l"(d) : "l"(a), "l"(b), "l"(c));
    return d;
}
static __device__ __forceinline__ unsigned long long mul2(unsigned long long a, unsigned long long b) {
    unsigned long long d;
    asm("mul.rn.f32x2 %0, %1, %2;" : "=l"(d) : "l"(a), "l"(b));
    return d;
}

// =======================================================================
// K1: partial Bx over e-slice. grid (64, 8), block 256 (8 warps).
// Warp owns 32 rows (one per lane); x staged through a 32x32 xor-swizzled
// smem tile (coalesced LDG.128, conflict-free STS/LDS); B-slice broadcast.
// =======================================================================
__global__ void __launch_bounds__(256, 4) k_bx(const float* __restrict__ x,
                                               const float* __restrict__ Bin)
{
    __shared__ float sB[EB * D_STATE];   // 8 KB
    __shared__ float xt[8][32 * 32];     // 32 KB

    const int tid  = threadIdx.x;
    const int w    = tid >> 5;
    const int lane = tid & 31;
    const int eBase   = blockIdx.y * EB;
    const int rowBase = blockIdx.x * 256 + w * 32;

    // load B slice (coalesced float4)
    {
        const float4* B4 = (const float4*)(Bin + eBase * D_STATE);
        float4* sB4 = (float4*)sB;
        #pragma unroll
        for (int i = tid; i < EB * 4; i += 256) sB4[i] = B4[i];
    }
    __syncthreads();

    unsigned long long acc[8];
    #pragma unroll
    for (int j = 0; j < 8; j++) acc[j] = 0ull;

    const ulonglong2* sBu = (const ulonglong2*)sB;
    const float4* x4 = (const float4*)x;
    float* xtw = xt[w];

    const int rlo = lane >> 3;          // 0..3
    const int c4  = (lane & 7) * 4;     // 0,4,..,28

    #pragma unroll
    for (int t = 0; t < 4; t++) {
        const int eb4 = (eBase >> 2) + t * 8;
        __syncwarp();
        // stage 32 rows x 32 e's: 8 coalesced LDG.128 per lane
        #pragma unroll
        for (int j = 0; j < 8; j++) {
            int rr = j * 4 + rlo;
            float4 xv = __ldg(x4 + (size_t)(rowBase + rr) * 256 + eb4 + (lane & 7));
            xtw[(c4 + 0) * 32 + (rr ^ (c4 + 0))] = xv.x;
            xtw[(c4 + 1) * 32 + (rr ^ (c4 + 1))] = xv.y;
            xtw[(c4 + 2) * 32 + (rr ^ (c4 + 2))] = xv.z;
            xtw[(c4 + 3) * 32 + (rr ^ (c4 + 3))] = xv.w;
        }
        __syncwarp();
        // compute: per e, broadcast B row, per-lane x, 8 f32x2 FMAs
        #pragma unroll
        for (int el = 0; el < 32; el++) {
            float xv = xtw[el * 32 + (lane ^ el)];
            unsigned long long xx = pack2(xv, xv);
            int e = t * 32 + el;
            ulonglong2 q0 = sBu[e * 4 + 0];
            ulonglong2 q1 = sBu[e * 4 + 1];
            ulonglong2 q2 = sBu[e * 4 + 2];
            ulonglong2 q3 = sBu[e * 4 + 3];
            acc[0] = fma2(q0.x, xx, acc[0]);
            acc[1] = fma2(q0.y, xx, acc[1]);
            acc[2] = fma2(q1.x, xx, acc[2]);
            acc[3] = fma2(q1.y, xx, acc[3]);
            acc[4] = fma2(q2.x, xx, acc[4]);
            acc[5] = fma2(q2.y, xx, acc[5]);
            acc[6] = fma2(q3.x, xx, acc[6]);
            acc[7] = fma2(q3.y, xx, acc[7]);
        }
    }

    // write partial (per-row 64B)
    const int row = rowBase + lane;
    float v[16];
    #pragma unroll
    for (int j = 0; j < 8; j++) unpack2(acc[j], v[2 * j], v[2 * j + 1]);
    float4* gp = (float4*)(&g_bxp[blockIdx.y][row * D_STATE]);
    #pragma unroll
    for (int q = 0; q < 4; q++)
        gp[q] = make_float4(v[4 * q], v[4 * q + 1], v[4 * q + 2], v[4 * q + 3]);
}

// =======================================================================
// K1.5: sum partials, softplus, decay. 65536 threads, one float4 each.
// =======================================================================
__global__ void __launch_bounds__(256) k_combine(const float* __restrict__ A)
{
    const int idx = blockIdx.x * 256 + threadIdx.x;   // float4 index
    float4 s = make_float4(0.f, 0.f, 0.f, 0.f);
    #pragma unroll
    for (int p = 0; p < ESPLIT; p++) {
        float4 v = __ldg((const float4*)g_bxp[p] + idx);
        s.x += v.x; s.y += v.y; s.z += v.z; s.w += v.w;
    }
    const int q = (idx & 3) * 4;
    float4 d;
    {
        float a0 = -expf(__ldg(A + q + 0));
        float a1 = -expf(__ldg(A + q + 1));
        float a2 = -expf(__ldg(A + q + 2));
        float a3 = -expf(__ldg(A + q + 3));
        float sp;
        sp = fmaxf(s.x, 0.f) + log1pf(expf(-fabsf(s.x))); d.x = expf(sp * a0);
        sp = fmaxf(s.y, 0.f) + log1pf(expf(-fabsf(s.y))); d.y = expf(sp * a1);
        sp = fmaxf(s.z, 0.f) + log1pf(expf(-fabsf(s.z))); d.z = expf(sp * a2);
        sp = fmaxf(s.w, 0.f) + log1pf(expf(-fabsf(s.w))); d.w = expf(sp * a3);
    }
    ((float4*)g_bx)[idx]    = s;
    ((float4*)g_decay)[idx] = d;
}

// =======================================================================
// K2: 128 chunk aggregates per batch (32 steps each) + boundary scan.
// block 1024: thread (c,s) handles chunks c and c+64.
// =======================================================================
__global__ void __launch_bounds__(1024) k_scan()
{
    __shared__ float sa[NCHUNK2 * D_STATE];   // 8 KB
    __shared__ float sv[NCHUNK2 * D_STATE];   // 8 KB
    const int b   = blockIdx.x;
    const int tid = threadIdx.x;
    const int c0  = tid >> 4;       // 0..63
    const int s   = tid & 15;

    #pragma unroll
    for (int half = 0; half < 2; half++) {
        const int cc = c0 + half * 64;
        int base = (b * SEQLEN + cc * CHUNK2) * D_STATE + s;
        float a = 1.0f, v = 0.0f;
        #pragma unroll 4
        for (int t = 0; t < CHUNK2; t++) {
            float d   = g_decay[base + t * D_STATE];
            float bxv = g_bx   [base + t * D_STATE];
            v = fmaf(v, d, bxv);
            a *= d;
        }
        sa[cc * 16 + s] = a;
        sv[cc * 16 + s] = v;
    }
    __syncthreads();

    if (tid < 16) {
        float h = 0.0f;
        for (int cc = 0; cc < NCHUNK2; cc++) {
            g_h0[(b * NCHUNK2 + cc) * 16 + tid] = h;
            h = fmaf(sa[cc * 16 + tid], h, sv[cc * 16 + tid]);
        }
    }
}

// =======================================================================
// K3: per-chunk (32 rows) local scan + y = h @ C + x*D
// grid = BATCH*NCHUNK2 = 512 blocks x 256 threads.
// =======================================================================
__global__ void __launch_bounds__(256) k_out(const float* __restrict__ x,
                                             const float* __restrict__ C,
                                             const float* __restrict__ D,
                                             float* __restrict__ y)
{
    __shared__ __align__(16) float hh[CHUNK2][16];
    const int b    = blockIdx.x >> 7;       // /128
    const int c    = blockIdx.x & 127;
    const int tid  = threadIdx.x;
    const int row0 = b * SEQLEN + c * CHUNK2;

    unsigned long long ca[16], cb[16];
    #pragma unroll
    for (int s = 0; s < 16; s++) {
        float4 cv = __ldg((const float4*)C + s * 256 + tid);
        ca[s] = pack2(cv.x, cv.y);
        cb[s] = pack2(cv.z, cv.w);
    }
    float4 dv = __ldg((const float4*)D + tid);
    bool anyD = (dv.x != 0.0f) || (dv.y != 0.0f) || (dv.z != 0.0f) || (dv.w != 0.0f);
    unsigned long long d01 = pack2(dv.x, dv.y);
    unsigned long long d23 = pack2(dv.z, dv.w);

    // local 32-step scan by lanes 0..15, software-pipelined 8-at-a-time
    if (tid < 16) {
        float h = g_h0[(b * NCHUNK2 + c) * 16 + tid];
        int base = row0 * D_STATE + tid;
        float dA[8], vA[8], dB[8], vB[8];
        #pragma unroll
        for (int k = 0; k < 8; k++) {
            dA[k] = g_decay[base + k * 16];
            vA[k] = g_bx   [base + k * 16];
        }
        #pragma unroll
        for (int g = 0; g < 4; g++) {
            if (g < 3) {
                #pragma unroll
                for (int k = 0; k < 8; k++) {
                    dB[k] = g_decay[base + ((g + 1) * 8 + k) * 16];
                    vB[k] = g_bx   [base + ((g + 1) * 8 + k) * 16];
                }
            }
            #pragma unroll
            for (int k = 0; k < 8; k++) {
                h = fmaf(h, dA[k], vA[k]);
                hh[g * 8 + k][tid] = h;
            }
            #pragma unroll
            for (int k = 0; k < 8; k++) { dA[k] = dB[k]; vA[k] = vB[k]; }
        }
    }
    __syncthreads();

    const float4* x4 = (const float4*)x;
    float4* y4 = (float4*)y;

    #pragma unroll 2
    for (int t = 0; t < CHUNK2; t++) {
        unsigned long long y01, y23;
        if (anyD) {
            float4 xv = __ldg(x4 + (size_t)(row0 + t) * 256 + tid);
            y01 = mul2(pack2(xv.x, xv.y), d01);
            y23 = mul2(pack2(xv.z, xv.w), d23);
        } else {
            y01 = 0ull; y23 = 0ull;
        }
        const float4* hf = (const float4*)hh[t];
        float4 h0 = hf[0], h1 = hf[1], h2 = hf[2], h3 = hf[3];

        #define SSTEP(hv, s) { unsigned long long hs = pack2((hv), (hv)); \
                               y01 = fma2(hs, ca[s], y01);                \
                               y23 = fma2(hs, cb[s], y23); }
        SSTEP(h0.x, 0)  SSTEP(h0.y, 1)  SSTEP(h0.z, 2)  SSTEP(h0.w, 3)
        SSTEP(h1.x, 4)  SSTEP(h1.y, 5)  SSTEP(h1.z, 6)  SSTEP(h1.w, 7)
        SSTEP(h2.x, 8)  SSTEP(h2.y, 9)  SSTEP(h2.z,10)  SSTEP(h2.w,11)
        SSTEP(h3.x,12)  SSTEP(h3.y,13)  SSTEP(h3.z,14)  SSTEP(h3.w,15)
        #undef SSTEP

        float4 out;
        unpack2(y01, out.x, out.y);
        unpack2(y23, out.z, out.w);
        y4[(size_t)(row0 + t) * 256 + tid] = out;
    }
}

// =======================================================================
extern "C" void kernel_launch(void* const* d_in, const int* in_sizes, int n_in,
                              void* d_out, int out_size)
{
    const float* x   = (const float*)d_in[0];
    const float* A   = (const float*)d_in[1];
    const float* Bin = (const float*)d_in[2];
    const float* C   = (const float*)d_in[3];
    const float* D   = (const float*)d_in[4];
    float* y = (float*)d_out;

    dim3 g1(NROWS / 256, ESPLIT);
    k_bx<<<g1, 256>>>(x, Bin);
    k_combine<<<(NROWS * 4) / 256, 256>>>(A);
    k_scan<<<BATCH, 1024>>>();
    k_out<<<BATCH * NCHUNK2, 256>>>(x, C, D, y);
}